// round 2
// baseline (speedup 1.0000x reference)
#include <cuda_runtime.h>
#include <cuda_bf16.h>
#include <cstdint>

// GraphSAGE 2-layer, D=64, fp32.
//   layer: out = h @ W_self + (segment_mean over dst of h[src]) @ W_neigh + b
//   h1 = relu(layer1(x)); out = layer2(h1)
//
// Inputs (metadata order):
//   0: x        [N,64] f32
//   1: src      [E]    i32
//   2: dst      [E]    i32
//   3: W1_self  [64,64] f32
//   4: W1_neigh [64,64] f32
//   5: b1       [64]   f32
//   6: W2_self  [64,64] f32
//   7: W2_neigh [64,64] f32
//   8: b2       [64]   f32
// Output: [N,64] f32
//
// NOTE: kernel_launch contains ONLY kernel launches (no runtime API calls at
// all) so graph capture sees exactly 6 nodes. Scratch lives in __device__
// globals; routing between layer-1 output (g_h1) and harness buffers is done
// with template flags resolved in device code.

#define D 64
#define MAXN 50048

__device__ float g_sum[MAXN * D];   // scratch: segment sums
__device__ float g_deg[MAXN];       // scratch: in-degrees (float)
__device__ float g_h1[MAXN * D];    // scratch: layer-1 activations

// ---------------------------------------------------------------------------
// Zero the segment-sum buffer (and optionally degrees).
// ---------------------------------------------------------------------------
__global__ void zero_kernel(int n, int zero_deg) {
    int total4 = n * (D / 4);
    for (int i = blockIdx.x * blockDim.x + threadIdx.x; i < total4;
         i += gridDim.x * blockDim.x) {
        reinterpret_cast<float4*>(g_sum)[i] = make_float4(0.f, 0.f, 0.f, 0.f);
    }
    if (zero_deg) {
        for (int i = blockIdx.x * blockDim.x + threadIdx.x; i < n;
             i += gridDim.x * blockDim.x) {
            g_deg[i] = 0.f;
        }
    }
}

// ---------------------------------------------------------------------------
// Edge scatter: 16 threads per edge, each moves one float4 chunk.
// sum[dst] += h[src]; optionally deg[dst] += 1.
// FROM_H1: read activations from g_h1 instead of the kernel argument.
// ---------------------------------------------------------------------------
template <bool FROM_H1, bool COUNT_DEG>
__global__ void __launch_bounds__(256)
scatter_kernel(const float* __restrict__ h_in,
               const int* __restrict__ src,
               const int* __restrict__ dst,
               int E) {
    const float* __restrict__ h = FROM_H1 ? (const float*)g_h1 : h_in;

    long long idx = (long long)blockIdx.x * blockDim.x + threadIdx.x;
    int e = (int)(idx >> 4);
    if (e >= E) return;
    int c = ((int)idx & 15) * 4;

    int s = __ldg(src + e);
    int d = __ldg(dst + e);

    float4 v = *reinterpret_cast<const float4*>(h + (size_t)s * D + c);
    float* p = g_sum + (size_t)d * D + c;
    asm volatile("red.global.add.v4.f32 [%0], {%1,%2,%3,%4};"
                 :: "l"(p), "f"(v.x), "f"(v.y), "f"(v.z), "f"(v.w)
                 : "memory");
    if (COUNT_DEG && c == 0) {
        asm volatile("red.global.add.f32 [%0], %1;"
                     :: "l"(g_deg + d), "f"(1.0f) : "memory");
    }
}

// ---------------------------------------------------------------------------
// Fused: mean = sum/max(deg,1); out = h@W_self + mean@W_neigh + b  [+ relu]
// Block = 256 threads = 16 nodes x 16 col-groups (4 cols each).
// Both weight matrices + 16 x-rows + 16 mean-rows staged in shared (40 KB).
// FROM_H1 / TO_H1 route activations through the g_h1 scratch buffer.
// ---------------------------------------------------------------------------
template <bool RELU, bool FROM_H1, bool TO_H1>
__global__ void __launch_bounds__(256)
combine_kernel(const float* __restrict__ h_in,
               const float* __restrict__ Wself,
               const float* __restrict__ Wneigh,
               const float* __restrict__ bias,
               float* __restrict__ out_in, int n) {
    const float* __restrict__ h  = FROM_H1 ? (const float*)g_h1 : h_in;
    float* __restrict__ out      = TO_H1 ? (float*)g_h1 : out_in;

    __shared__ float sWs[D * D];     // 16 KB
    __shared__ float sWn[D * D];     // 16 KB
    __shared__ float sX[16 * D];     // 4 KB
    __shared__ float sM[16 * D];     // 4 KB

    int tid = threadIdx.x;
    int node0 = blockIdx.x * 16;

    // Stage weights (coalesced float4).
    for (int i = tid; i < D * D / 4; i += 256) {
        reinterpret_cast<float4*>(sWs)[i] =
            reinterpret_cast<const float4*>(Wself)[i];
        reinterpret_cast<float4*>(sWn)[i] =
            reinterpret_cast<const float4*>(Wneigh)[i];
    }
    // Stage node rows + compute mean on the fly.
    for (int i = tid; i < 16 * D / 4; i += 256) {
        int nl = i >> 4;                 // node-local (16 float4 per row)
        int k4 = i & 15;
        int node = node0 + nl;
        if (node < n) {
            float4 xv = reinterpret_cast<const float4*>(h + (size_t)node * D)[k4];
            float4 sv = reinterpret_cast<const float4*>(g_sum + (size_t)node * D)[k4];
            float inv = 1.0f / fmaxf(g_deg[node], 1.0f);
            reinterpret_cast<float4*>(sX)[i] = xv;
            reinterpret_cast<float4*>(sM)[i] =
                make_float4(sv.x * inv, sv.y * inv, sv.z * inv, sv.w * inv);
        } else {
            reinterpret_cast<float4*>(sX)[i] = make_float4(0.f, 0.f, 0.f, 0.f);
            reinterpret_cast<float4*>(sM)[i] = make_float4(0.f, 0.f, 0.f, 0.f);
        }
    }
    __syncthreads();

    int nl = tid >> 4;      // 0..15 node within block
    int cg = tid & 15;      // 0..15 column group
    int c0 = cg * 4;

    float a0 = bias[c0 + 0];
    float a1 = bias[c0 + 1];
    float a2 = bias[c0 + 2];
    float a3 = bias[c0 + 3];

    const float* xr = sX + nl * D;
    const float* mr = sM + nl * D;

#pragma unroll
    for (int k = 0; k < D; k++) {
        float xv = xr[k];
        float mv = mr[k];
        float4 ws = *reinterpret_cast<const float4*>(sWs + k * D + c0);
        float4 wn = *reinterpret_cast<const float4*>(sWn + k * D + c0);
        a0 += xv * ws.x + mv * wn.x;
        a1 += xv * ws.y + mv * wn.y;
        a2 += xv * ws.z + mv * wn.z;
        a3 += xv * ws.w + mv * wn.w;
    }

    int node = node0 + nl;
    if (node < n) {
        if (RELU) {
            a0 = fmaxf(a0, 0.f); a1 = fmaxf(a1, 0.f);
            a2 = fmaxf(a2, 0.f); a3 = fmaxf(a3, 0.f);
        }
        *reinterpret_cast<float4*>(out + (size_t)node * D + c0) =
            make_float4(a0, a1, a2, a3);
    }
}

// ---------------------------------------------------------------------------
extern "C" void kernel_launch(void* const* d_in, const int* in_sizes, int n_in,
                              void* d_out, int out_size) {
    const float* x       = (const float*)d_in[0];
    const int*   src     = (const int*)d_in[1];
    const int*   dst     = (const int*)d_in[2];
    const float* W1_self = (const float*)d_in[3];
    const float* W1_neigh= (const float*)d_in[4];
    const float* b1      = (const float*)d_in[5];
    const float* W2_self = (const float*)d_in[6];
    const float* W2_neigh= (const float*)d_in[7];
    const float* b2      = (const float*)d_in[8];
    float* out = (float*)d_out;

    int n = in_sizes[0] / D;
    int E = in_sizes[1];

    int zblocks = 1024;
    long long sc_items = (long long)E * 16;
    int sc_blocks = (int)((sc_items + 255) / 256);
    int cb_blocks = (n + 15) / 16;

    // ---- layer 1 ----  (x -> g_h1, relu)
    zero_kernel<<<zblocks, 256>>>(n, 1);
    scatter_kernel<false, true><<<sc_blocks, 256>>>(x, src, dst, E);
    combine_kernel<true, false, true>
        <<<cb_blocks, 256>>>(x, W1_self, W1_neigh, b1, nullptr, n);

    // ---- layer 2 ----  (g_h1 -> out)
    zero_kernel<<<zblocks, 256>>>(n, 0);
    scatter_kernel<true, false><<<sc_blocks, 256>>>(nullptr, src, dst, E);
    combine_kernel<false, true, false>
        <<<cb_blocks, 256>>>(nullptr, W2_self, W2_neigh, b2, out, n);
}